// round 5
// baseline (speedup 1.0000x reference)
#include <cuda_runtime.h>
#include <cuda_bf16.h>
#include <cstdint>

// Problem constants
#define B_   2048
#define MND  128
#define D_   512
#define H_   512
#define KF   2048    // fp32 K (concat of 4x512)
#define KBF  6144    // bf16-split K = 3*2048 : A'=[Xhi|Xhi|Xlo], B'=[Whi|Wlo|Whi]
#define CHROWS 512   // batch chunk rows for means/gemm overlap
#define NCH    4

// Scratch (device globals; no allocations allowed)
__device__ __nv_bfloat16 g_Xbf[(size_t)B_ * KBF];   // 25.2 MB
__device__ __nv_bfloat16 g_Wbf[(size_t)H_ * KBF];   // 6.3 MB
__device__ float g_Wbig[(size_t)H_ * KF];           // assembled fp32 weights
__device__ float g_Wrc[H_ * H_];                    // W_r_img + W_r_txt
__device__ float g_bc[H_];                          // combined bias

// ---------------------------------------------------------------------------
__device__ __forceinline__ void bfsplit(float x, __nv_bfloat16& hi, __nv_bfloat16& lo) {
    hi = __float2bfloat16_rn(x);
    lo = __float2bfloat16_rn(x - __bfloat162float(hi));
}
__device__ __forceinline__ uint32_t pack2(__nv_bfloat16 a, __nv_bfloat16 b) {
    return (uint32_t)__bfloat16_as_ushort(a) | ((uint32_t)__bfloat16_as_ushort(b) << 16);
}

// ---------------------------------------------------------------------------
// prep: Wbig[:,0:512]=W_l_img, Wbig[:,512:1024]=W_l_txt (fp32), Wrc = sum
// ---------------------------------------------------------------------------
__global__ void prep_kernel(const float* __restrict__ Wl_img,
                            const float* __restrict__ Wl_txt,
                            const float* __restrict__ Wr_img,
                            const float* __restrict__ Wr_txt) {
    int idx = blockIdx.x * blockDim.x + threadIdx.x;
    if (idx < H_ * 1024) {
        int h = idx >> 10, c = idx & 1023;
        float v = (c < 512) ? Wl_img[h * 512 + c] : Wl_txt[h * 512 + (c - 512)];
        g_Wbig[h * KF + c] = v;
    }
    if (idx < H_ * H_) g_Wrc[idx] = Wr_img[idx] + Wr_txt[idx];
}

// ---------------------------------------------------------------------------
// Wc = Wrc @ W_user  (512x1024x512) exact fp32 -> Wbig cols [1024,2048)
// ---------------------------------------------------------------------------
__global__ void gemm_nn_wc(const float* __restrict__ Wuser) {
    __shared__ float As[16][68];
    __shared__ float Bs[16][68];
    const int bn = blockIdx.x, bm = blockIdx.y, tid = threadIdx.x;
    const int tn = tid & 15, tm = tid >> 4;
    const int ar = tid >> 2, akv = tid & 3;
    const int brow = tid >> 4, bc4 = tid & 15;

    const float* Ap = g_Wrc + (size_t)(bm * 64 + ar) * 512 + akv * 4;
    const float* Bp = Wuser + (size_t)brow * 1024 + bn * 64 + bc4 * 4;

    float acc[4][4] = {};
    for (int k0 = 0; k0 < 512; k0 += 16) {
        float4 av = *(const float4*)(Ap + k0);
        float4 bv = *(const float4*)(Bp + (size_t)k0 * 1024);
        __syncthreads();
        As[akv*4+0][ar]=av.x; As[akv*4+1][ar]=av.y; As[akv*4+2][ar]=av.z; As[akv*4+3][ar]=av.w;
        *(float4*)&Bs[brow][bc4 * 4] = bv;
        __syncthreads();
        #pragma unroll
        for (int k = 0; k < 16; k++) {
            float4 a = *(const float4*)&As[k][tm * 4];
            float4 b = *(const float4*)&Bs[k][tn * 4];
            acc[0][0]+=a.x*b.x; acc[0][1]+=a.x*b.y; acc[0][2]+=a.x*b.z; acc[0][3]+=a.x*b.w;
            acc[1][0]+=a.y*b.x; acc[1][1]+=a.y*b.y; acc[1][2]+=a.y*b.z; acc[1][3]+=a.y*b.w;
            acc[2][0]+=a.z*b.x; acc[2][1]+=a.z*b.y; acc[2][2]+=a.z*b.z; acc[2][3]+=a.z*b.w;
            acc[3][0]+=a.w*b.x; acc[3][1]+=a.w*b.y; acc[3][2]+=a.w*b.z; acc[3][3]+=a.w*b.w;
        }
    }
    int row = bm * 64 + tm * 4, col = bn * 64 + tn * 4;
    #pragma unroll
    for (int i = 0; i < 4; i++)
        *(float4*)&g_Wbig[(size_t)(row + i) * KF + 1024 + col] =
            make_float4(acc[i][0], acc[i][1], acc[i][2], acc[i][3]);
}

// ---------------------------------------------------------------------------
// wconv: g_Wbig fp32 [512,2048] -> g_Wbf [512,6144] = [Whi | Wlo | Whi]
// ---------------------------------------------------------------------------
__global__ void wconv_kernel() {
    int idx = blockIdx.x * blockDim.x + threadIdx.x;
    if (idx >= H_ * KF) return;
    int h = idx >> 11, j = idx & 2047;
    float w = g_Wbig[(size_t)h * KF + j];
    __nv_bfloat16 hi, lo; bfsplit(w, hi, lo);
    __nv_bfloat16* row = g_Wbf + (size_t)h * KBF;
    row[j] = hi; row[2048 + j] = lo; row[4096 + j] = hi;
}

// ---------------------------------------------------------------------------
// bc[h] = b_l_img[h] + b_l_txt[h] + sum_k Wrc[h,k] * b_user[k]   (exact fp32)
// ---------------------------------------------------------------------------
__global__ void bc_kernel(const float* __restrict__ b_user,
                          const float* __restrict__ bl_img,
                          const float* __restrict__ bl_txt) {
    int h = blockIdx.x, t = threadIdx.x;
    float s = 0.0f;
    for (int k = t; k < H_; k += 128) s += g_Wrc[h * H_ + k] * b_user[k];
    __shared__ float red[4];
    #pragma unroll
    for (int o = 16; o; o >>= 1) s += __shfl_down_sync(0xffffffffu, s, o);
    if ((t & 31) == 0) red[t >> 5] = s;
    __syncthreads();
    if (t == 0) g_bc[h] = red[0] + red[1] + red[2] + red[3] + bl_img[h] + bl_txt[h];
}

// ---------------------------------------------------------------------------
// means chunk: for b in [b0, b0+CHROWS):
//   Xbf[b] = split([img_mean | txt_mean | it | ii]) as [Xhi | Xhi | Xlo]
// ---------------------------------------------------------------------------
__global__ void means_kernel(const float* __restrict__ img,
                             const float* __restrict__ txt,
                             const float* __restrict__ it,
                             const float* __restrict__ ii,
                             int b0) {
    int b = b0 + blockIdx.x;
    int t = threadIdx.x;
    int h4 = t & 127;
    const bool isimg = (t < 128);
    const float* src = isimg ? img : txt;
    const float4* base = (const float4*)(src + (size_t)b * MND * H_) + h4;

    float4 acc = make_float4(0.f, 0.f, 0.f, 0.f);
    #pragma unroll 16
    for (int m = 0; m < MND; m++) {
        float4 v = base[(size_t)m * (H_ / 4)];
        acc.x += v.x; acc.y += v.y; acc.z += v.z; acc.w += v.w;
    }
    const float inv = 1.0f / (float)MND;
    acc.x *= inv; acc.y *= inv; acc.z *= inv; acc.w *= inv;

    __nv_bfloat16* row = g_Xbf + (size_t)b * KBF;

    __nv_bfloat16 h0,h1,h2,h3,l0,l1,l2,l3;
    bfsplit(acc.x,h0,l0); bfsplit(acc.y,h1,l1); bfsplit(acc.z,h2,l2); bfsplit(acc.w,h3,l3);
    uint2 phi = make_uint2(pack2(h0,h1), pack2(h2,h3));
    uint2 plo = make_uint2(pack2(l0,l1), pack2(l2,l3));
    int c0 = (isimg ? 0 : 512) + h4 * 4;
    *(uint2*)(row + c0)        = phi;
    *(uint2*)(row + 2048 + c0) = phi;
    *(uint2*)(row + 4096 + c0) = plo;

    const float4* cs = (const float4*)((isimg ? it : ii) + (size_t)b * D_);
    float4 c = cs[h4];
    bfsplit(c.x,h0,l0); bfsplit(c.y,h1,l1); bfsplit(c.z,h2,l2); bfsplit(c.w,h3,l3);
    phi = make_uint2(pack2(h0,h1), pack2(h2,h3));
    plo = make_uint2(pack2(l0,l1), pack2(l2,l3));
    int c1 = (isimg ? 1024 : 1536) + h4 * 4;
    *(uint2*)(row + c1)        = phi;
    *(uint2*)(row + 2048 + c1) = phi;
    *(uint2*)(row + 4096 + c1) = plo;
}

// ---------------------------------------------------------------------------
// bf16 legacy-mma GEMM chunk: out[rows] = relu( A' @ B'^T + bc )
// BM=64, BN=64, BK=64 bf16, 256 thr (8 warps, 4m x 2n, warp tile 16x32).
// ldmatrix.x4 fragment loads; smem row stride 72 bf16 (144B) -> conflict-free.
// cp.async 3-stage pipeline.
// ---------------------------------------------------------------------------
#define GBM 64
#define GBN 64
#define BKE 64
#define STRE 72
#define NST 3
#define SA_BYTES (GBM * STRE * 2)      // 9216
#define STG_BYTES (2 * SA_BYTES)       // 18432 (A + B)
#define SM_TOT (NST * STG_BYTES)       // 55296
#define NKT (KBF / BKE)                // 96

__device__ __forceinline__ void cp16(uint32_t s, const void* g) {
    asm volatile("cp.async.cg.shared.global [%0], [%1], 16;\n" :: "r"(s), "l"(g));
}
#define LDSM4(r, addr) \
    asm volatile("ldmatrix.sync.aligned.m8n8.x4.shared.b16 {%0,%1,%2,%3}, [%4];" \
        : "=r"((r)[0]), "=r"((r)[1]), "=r"((r)[2]), "=r"((r)[3]) : "r"(addr))
#define MMA16816(d, a, B0, B1) \
    asm volatile("mma.sync.aligned.m16n8k16.row.col.f32.bf16.bf16.f32 " \
        "{%0,%1,%2,%3},{%4,%5,%6,%7},{%8,%9},{%0,%1,%2,%3};" \
        : "+f"((d)[0]), "+f"((d)[1]), "+f"((d)[2]), "+f"((d)[3]) \
        : "r"((a)[0]), "r"((a)[1]), "r"((a)[2]), "r"((a)[3]), "r"(B0), "r"(B1))

__global__ __launch_bounds__(256) void gemm_bf16(float* __restrict__ C, int rowoff) {
    extern __shared__ char smem[];
    uint32_t sb;
    asm("{ .reg .u64 t; cvta.to.shared.u64 t, %1; cvt.u32.u64 %0, t; }"
        : "=r"(sb) : "l"(smem));

    const int tid  = threadIdx.x;
    const int w    = tid >> 5;
    const int lane = tid & 31;
    const int bn0  = blockIdx.x * GBN;
    const int bm0  = rowoff + blockIdx.y * GBM;
    const int wm   = (w & 3) * 16;
    const int wn   = (w >> 2) * 32;

    const __nv_bfloat16* Ag = g_Xbf + (size_t)bm0 * KBF;
    const __nv_bfloat16* Bg = g_Wbf + (size_t)bn0 * KBF;
    const int lr = tid >> 3;          // 0..31
    const int lc = tid & 7;           // 16B chunk in row

    // fragment smem byte offsets (within stage A / stage B bases)
    const uint32_t aoff  = (uint32_t)((wm + (lane & 15)) * STRE + ((lane >> 4) << 3)) * 2;
    const uint32_t boff0 = (uint32_t)((wn + (lane & 7) + ((lane >> 4) << 3)) * STRE
                                      + (((lane >> 3) & 1) << 3)) * 2;
    const uint32_t boff1 = boff0 + (uint32_t)(16 * STRE * 2);

    auto issue = [&](int st, int kt) {
        const int kb = kt * BKE;
        uint32_t a0 = sb + st * STG_BYTES;
        uint32_t b0 = a0 + SA_BYTES;
        #pragma unroll
        for (int i = 0; i < 2; i++) {
            int r = lr + i * 32;
            uint32_t off = (uint32_t)(r * STRE + lc * 8) * 2;
            cp16(a0 + off, Ag + (size_t)r * KBF + kb + lc * 8);
            cp16(b0 + off, Bg + (size_t)r * KBF + kb + lc * 8);
        }
    };

    float acc[4][4] = {};

    #pragma unroll
    for (int s = 0; s < NST; s++) {
        issue(s, s);
        asm volatile("cp.async.commit_group;\n" ::: "memory");
    }

    for (int kt = 0; kt < NKT; kt++) {
        const int st = kt % NST;
        asm volatile("cp.async.wait_group %0;\n" :: "n"(NST - 1) : "memory");
        __syncthreads();

        const uint32_t ab = sb + st * STG_BYTES;
        const uint32_t bb = ab + SA_BYTES;

        #pragma unroll
        for (int ks = 0; ks < 4; ks++) {
            uint32_t a[4], p0[4], p1[4];
            LDSM4(a,  ab + aoff  + ks * 32);
            LDSM4(p0, bb + boff0 + ks * 32);
            LDSM4(p1, bb + boff1 + ks * 32);
            MMA16816(acc[0], a, p0[0], p0[1]);
            MMA16816(acc[1], a, p0[2], p0[3]);
            MMA16816(acc[2], a, p1[0], p1[1]);
            MMA16816(acc[3], a, p1[2], p1[3]);
        }

        __syncthreads();
        if (kt + NST < NKT) issue(st, kt + NST);
        asm volatile("cp.async.commit_group;\n" ::: "memory");
    }

    // epilogue: bias + ReLU
    const int g  = lane >> 2;
    const int tg = lane & 3;
    const int row = bm0 + wm + g;
    #pragma unroll
    for (int ni = 0; ni < 4; ni++) {
        const int col = bn0 + wn + ni * 8 + tg * 2;
        const float b0v = g_bc[col], b1v = g_bc[col + 1];
        float2 v0, v1;
        v0.x = fmaxf(acc[ni][0] + b0v, 0.f);
        v0.y = fmaxf(acc[ni][1] + b1v, 0.f);
        v1.x = fmaxf(acc[ni][2] + b0v, 0.f);
        v1.y = fmaxf(acc[ni][3] + b1v, 0.f);
        *(float2*)&C[(size_t)row * H_ + col]       = v0;
        *(float2*)&C[(size_t)(row + 8) * H_ + col] = v1;
    }
}

// ---------------------------------------------------------------------------
extern "C" void kernel_launch(void* const* d_in, const int* in_sizes, int n_in,
                              void* d_out, int out_size) {
    const float* it      = (const float*)d_in[0];
    const float* ii      = (const float*)d_in[1];
    const float* txt     = (const float*)d_in[2];
    const float* img     = (const float*)d_in[3];
    const float* W_user  = (const float*)d_in[4];
    const float* b_user  = (const float*)d_in[5];
    const float* Wl_img  = (const float*)d_in[6];
    const float* bl_img  = (const float*)d_in[7];
    const float* Wr_img  = (const float*)d_in[8];
    const float* Wl_txt  = (const float*)d_in[9];
    const float* bl_txt  = (const float*)d_in[10];
    const float* Wr_txt  = (const float*)d_in[11];
    float* out = (float*)d_out;

    cudaFuncSetAttribute(gemm_bf16,
                         cudaFuncAttributeMaxDynamicSharedMemorySize, SM_TOT);

    cudaStream_t s2;
    cudaEvent_t eFork, eJoin, evM[NCH];
    cudaStreamCreateWithFlags(&s2, cudaStreamNonBlocking);
    cudaEventCreateWithFlags(&eFork, cudaEventDisableTiming);
    cudaEventCreateWithFlags(&eJoin, cudaEventDisableTiming);
    for (int c = 0; c < NCH; c++)
        cudaEventCreateWithFlags(&evM[c], cudaEventDisableTiming);

    cudaEventRecord(eFork, 0);
    cudaStreamWaitEvent(s2, eFork, 0);

    // side stream: weight-prep chain (hidden under means chunk 0)
    prep_kernel<<<2048, 256, 0, s2>>>(Wl_img, Wl_txt, Wr_img, Wr_txt);
    {
        dim3 grid(1024 / 64, 512 / 64);
        gemm_nn_wc<<<grid, 256, 0, s2>>>(W_user);
    }
    wconv_kernel<<<(H_ * KF + 255) / 256, 256, 0, s2>>>();
    bc_kernel<<<512, 128, 0, s2>>>(b_user, bl_img, bl_txt);

    // chunked means (stream 0) -> gemm (stream s2) pipeline
    for (int c = 0; c < NCH; c++) {
        means_kernel<<<CHROWS, 256>>>(img, txt, it, ii, c * CHROWS);
        cudaEventRecord(evM[c], 0);
        cudaStreamWaitEvent(s2, evM[c], 0);
        dim3 grid(H_ / GBN, CHROWS / GBM);   // (8, 8) = 64 CTAs per chunk
        gemm_bf16<<<grid, 256, SM_TOT, s2>>>(out, c * CHROWS);
    }

    cudaEventRecord(eJoin, s2);
    cudaStreamWaitEvent(0, eJoin, 0);
}